// round 11
// baseline (speedup 1.0000x reference)
#include <cuda_runtime.h>

// Problem constants (from reference): N=32, RES=256, C=2, K=1024, T=1, EPS=1e-6
#define NB   32
#define RESO 256
#define KP   1024
#define EPSF 1e-6f
#define C1F  1.4426950408889634f          // log2(e)/T
#define UF   (C1F * C1F)                  // folded scale on squared distances
#define LN2F 0.6931471805599453f

// Scratch (no allocations allowed) --------------------------------------------
__device__ float g_sx[NB * KP];         // src.x + eps
__device__ float g_sy[NB * KP];         // src.y + eps
__device__ float g_sp[NB * KP];         // u * |src|^2
__device__ float g_tx[NB * KP];         // trg.x
__device__ float g_ty[NB * KP];         // trg.y
__device__ float g_part[1024];          // per-block weighted loss partials
__device__ float g_cnt [1024];          // per-block visibility counts
__device__ int   g_ctr = 0;             // last-block counter (self-resetting)

// MUFU intrinsics -------------------------------------------------------------
__device__ __forceinline__ float lg2a(float x) { float y; asm("lg2.approx.f32 %0, %1;" : "=f"(y) : "f"(x)); return y; }
__device__ __forceinline__ float ex2_neg(float x) {
    float y; asm("{ .reg .f32 t; neg.f32 t, %1; ex2.approx.f32 %0, t; }" : "=f"(y) : "f"(x)); return y;
}
__device__ __forceinline__ float sqrt_abs(float x) {
    float y; asm("{ .reg .f32 t; abs.f32 t, %1; sqrt.approx.f32 %0, t; }" : "=f"(y) : "f"(x)); return y;
}

// Packed f32x2 helpers --------------------------------------------------------
typedef unsigned long long u64;
__device__ __forceinline__ u64 pack2(float v) {
    u64 r; asm("mov.b64 %0, {%1, %1};" : "=l"(r) : "f"(v)); return r;
}
__device__ __forceinline__ u64 pack2f(float lo, float hi) {
    u64 r; asm("mov.b64 %0, {%1, %2};" : "=l"(r) : "f"(lo), "f"(hi)); return r;
}
__device__ __forceinline__ u64 add2(u64 a, u64 b) {
    u64 r; asm("add.rn.f32x2 %0, %1, %2;" : "=l"(r) : "l"(a), "l"(b)); return r;
}
__device__ __forceinline__ u64 fma2(u64 a, u64 b, u64 c) {
    u64 r; asm("fma.rn.f32x2 %0, %1, %2, %3;" : "=l"(r) : "l"(a), "l"(b), "l"(c)); return r;
}
__device__ __forceinline__ void unpack2(u64 p, float& lo, float& hi) {
    asm("mov.b64 {%0, %1}, %2;" : "=f"(lo), "=f"(hi) : "l"(p));
}

// Kernel 1: corner-parallel bilinear sampling (SoA outputs, src+trg) ----------
__global__ __launch_bounds__(256) void sample_kernel(
        const float* __restrict__ sflow, const float* __restrict__ tflow,
        const float* __restrict__ skp,  const float* __restrict__ tkp) {
    int g      = blockIdx.x * blockDim.x + threadIdx.x;    // [0, 262144)
    int samp   = g >> 2;                                   // [0, 2*N*K)
    int corner = g & 3;                                    // dx = c&1, dy = c>>1
    int k      = samp & (NB * KP - 1);                     // n*K + kp
    int n      = k >> 10;
    bool is_src = samp < NB * KP;

    const float* kp   = is_src ? skp   : tkp;
    const float* flow = is_src ? sflow : tflow;
    float2 p = ((const float2*)kp)[k];

    float x0f = floorf(p.x), y0f = floorf(p.y);
    float wx  = p.x - x0f,   wy  = p.y - y0f;
    int dx = corner & 1, dy = corner >> 1;
    int xi = (int)x0f + dx, yi = (int)y0f + dy;
    float w = (dx ? wx : 1.f - wx) * (dy ? wy : 1.f - wy);

    float ax = 0.f, ay = 0.f;
    if (xi >= 0 && xi < RESO && yi >= 0 && yi < RESO) {
        const float2 v = *(const float2*)(flow + ((((size_t)n * RESO + yi) * RESO + xi) << 1));
        ax = v.x * w;
        ay = v.y * w;
    }
    ax += __shfl_xor_sync(0xffffffffu, ax, 1);
    ay += __shfl_xor_sync(0xffffffffu, ay, 1);
    ax += __shfl_xor_sync(0xffffffffu, ax, 2);
    ay += __shfl_xor_sync(0xffffffffu, ay, 2);

    if (corner == 0) {
        if (is_src) {
            float sx = ax + EPSF, sy = ay + EPSF;          // fold +eps into src side
            g_sx[k] = sx;
            g_sy[k] = sy;
            g_sp[k] = UF * fmaf(sx, sx, sy * sy);          // u*|s|^2
        } else {
            g_tx[k] = ax;
            g_ty[k] = ay;
        }
    }
}

// Kernel 2: pairwise + CE diag + fused reduction ------------------------------
// exp via polynomial: t = C1*d (from sqrt of pre-scaled dsq); 2^-t computed as
// 2^-round(t) * poly(t - round(t)), poly = deg-4 Taylor on [-1/2, 1/2].
// Only MUFU op per pair: sqrt. 1 warp = 4 j's, block = 8 warps, grid = 1024.
__global__ __launch_bounds__(256) void pair_kernel(const int* __restrict__ vis,
                                                   const float* __restrict__ wt,
                                                   float* __restrict__ out) {
    __shared__ float shx[KP], shy[KP], shp[KP];            // src SoA for batch n (12 KB)
    __shared__ float sh_l[8], sh_v[8];
    __shared__ bool  s_last;
    const int warp = threadIdx.x >> 5, lane = threadIdx.x & 31;
    const int n     = blockIdx.x >> 5;                     // 32 blocks per batch
    const int jbase = ((blockIdx.x & 31) << 5) + (warp << 2);

    {   // vectorized smem fill: 256 float4 per array
        const float4* gx = (const float4*)(g_sx + n * KP);
        const float4* gy = (const float4*)(g_sy + n * KP);
        const float4* gp = (const float4*)(g_sp + n * KP);
        ((float4*)shx)[threadIdx.x] = gx[threadIdx.x];
        ((float4*)shy)[threadIdx.x] = gy[threadIdx.x];
        ((float4*)shp)[threadIdx.x] = gp[threadIdx.x];
    }
    __syncthreads();

    // per-j constants
    u64 qx2[4], qy2[4], rr2[4];
    float qxs[4], qys[4], rrs[4];
#pragma unroll
    for (int q = 0; q < 4; q++) {
        float txq = g_tx[n * KP + jbase + q];
        float tyq = g_ty[n * KP + jbase + q];
        qxs[q] = -2.f * UF * txq;
        qys[q] = -2.f * UF * tyq;
        rrs[q] = UF * fmaf(txq, txq, tyq * tyq);
        qx2[q] = pack2(qxs[q]);
        qy2[q] = pack2(qys[q]);
        rr2[q] = pack2(rrs[q]);
    }

    // packed constants for the exp polynomial
    const u64 MAGIC2  = pack2(12582912.0f);                // 1.5 * 2^23
    const u64 NMAGIC2 = pack2(-12582912.0f);
    const u64 NEG1_2  = pack2(-1.0f);
    const u64 ONE_2   = pack2(1.0f);
    const u64 Cc1 = pack2(-0.69314718056f);                // Taylor of 2^-f
    const u64 Cc2 = pack2( 0.24022650700f);
    const u64 Cc3 = pack2(-0.05550410866f);
    const u64 Cc4 = pack2( 0.00961812911f);

    u64 acc2[4] = {0ull, 0ull, 0ull, 0ull};                // packed f32x2 accumulators
    const u64* px = (const u64*)shx;                       // consecutive-i packed pairs
    const u64* py = (const u64*)shy;
    const u64* pp = (const u64*)shp;
#pragma unroll 2
    for (int it = 0; it < KP / 2; it += 32) {
        int pi = it + lane;
        u64 x2 = px[pi], y2 = py[pi], p2 = pp[pi];
#pragma unroll
        for (int q = 0; q < 4; q++) {
            // scaled squared distance for 2 pairs
            u64 d2 = fma2(x2, qx2[q], fma2(y2, qy2[q], add2(p2, rr2[q])));
            float dlo, dhi; unpack2(d2, dlo, dhi);
            float tlo = fminf(sqrt_abs(dlo), 100.f);       // t = C1*d, clamped
            float thi = fminf(sqrt_abs(dhi), 100.f);
            u64 tp = pack2f(tlo, thi);
            // split t = n + f (round-to-nearest), f in [-1/2, 1/2]
            u64 rp = add2(tp, MAGIC2);
            u64 ip = add2(rp, NMAGIC2);                    // n as float
            u64 fp = fma2(ip, NEG1_2, tp);                 // f = t - n
            // 2^-n via exponent bit construction (1 IMAD per scalar)
            float rlo, rhi; unpack2(rp, rlo, rhi);
            int slo = 0x3F800000 - __float_as_int(rlo) * 8388608;
            int shi = 0x3F800000 - __float_as_int(rhi) * 8388608;
            u64 sp = pack2f(__int_as_float(slo), __int_as_float(shi));
            // poly(f) ~= 2^-f, then acc += poly * 2^-n
            u64 pl = fma2(Cc4, fp, Cc3);
            pl = fma2(pl, fp, Cc2);
            pl = fma2(pl, fp, Cc1);
            pl = fma2(pl, fp, ONE_2);
            acc2[q] = fma2(pl, sp, acc2[q]);
        }
    }
    // collapse packed accumulators and warp-reduce
    float a[4];
#pragma unroll
    for (int q = 0; q < 4; q++) {
        float lo, hi; unpack2(acc2[q], lo, hi);
        a[q] = lo + hi;
#pragma unroll
        for (int o = 16; o; o >>= 1)
            a[q] += __shfl_xor_sync(0xffffffffu, a[q], o);
    }

    if (lane == 0) {
        float lsum = 0.f, vsum = 0.f;
#pragma unroll
        for (int q = 0; q < 4; q++) {
            int j = jbase + q;
            // scaled diagonal: v_jj = C1 * dist_jj (same dot form)
            float dsq = fmaf(shx[j], qxs[q], fmaf(shy[j], qys[q], shp[j] + rrs[q]));
            float vjj = sqrt_abs(dsq);
            // loss = 2*(ln(acc) + dist_jj) = 2*ln2*(lg2(acc) + v_jj)
            float loss = (2.f * LN2F) * (lg2a(a[q]) + vjj);
            float vi = vis[n * KP + j] ? 1.f : 0.f;
            lsum = fmaf(loss * wt[n * KP + j], vi, lsum);
            vsum += vi;
        }
        sh_l[warp] = lsum; sh_v[warp] = vsum;
    }
    __syncthreads();

    if (threadIdx.x == 0) {
        float l = 0.f, v = 0.f;
#pragma unroll
        for (int w = 0; w < 8; w++) { l += sh_l[w]; v += sh_v[w]; }
        g_part[blockIdx.x] = l;
        g_cnt [blockIdx.x] = v;
        __threadfence();
        int prev = atomicAdd(&g_ctr, 1);
        s_last = (prev == 1023);
    }
    __syncthreads();

    // Last block performs the final deterministic fixed-tree reduce.
    if (s_last) {
        __shared__ float fl[8], fv[8];
        float l = 0.f, v = 0.f;
#pragma unroll
        for (int r = 0; r < 4; r++) {
            int i = threadIdx.x + (r << 8);
            l += g_part[i];
            v += g_cnt [i];
        }
#pragma unroll
        for (int o = 16; o; o >>= 1) {
            l += __shfl_xor_sync(0xffffffffu, l, o);
            v += __shfl_xor_sync(0xffffffffu, v, o);
        }
        if (lane == 0) { fl[warp] = l; fv[warp] = v; }
        __syncthreads();
        if (threadIdx.x == 0) {
            l = 0.f; v = 0.f;
#pragma unroll
            for (int w = 0; w < 8; w++) { l += fl[w]; v += fv[w]; }
            out[0] = l / v;
            g_ctr = 0;                                     // reset for next graph replay
        }
    }
}

extern "C" void kernel_launch(void* const* d_in, const int* in_sizes, int n_in,
                              void* d_out, int out_size) {
    const float* sflow = (const float*)d_in[0];
    const float* tflow = (const float*)d_in[1];
    const float* skp   = (const float*)d_in[2];
    const float* tkp   = (const float*)d_in[3];
    const int*   vis   = (const int*)d_in[4];   // bool serialized as int32
    const float* wt    = (const float*)d_in[5];
    float*       out   = (float*)d_out;

    sample_kernel<<<(2 * NB * KP * 4) / 256, 256>>>(sflow, tflow, skp, tkp);
    pair_kernel<<<1024, 256>>>(vis, wt, out);
}

// round 13
// speedup vs baseline: 1.0462x; 1.0462x over previous
#include <cuda_runtime.h>

// Problem constants (from reference): N=32, RES=256, C=2, K=1024, T=1, EPS=1e-6
#define NB   32
#define RESO 256
#define KP   1024
#define EPSF 1e-6f
#define C1F  1.4426950408889634f          // log2(e)/T
#define UF   (C1F * C1F)                  // folded scale on squared distances
#define LN2F 0.6931471805599453f

// Scratch (no allocations allowed) --------------------------------------------
__device__ float g_sx[NB * KP];         // src.x + eps
__device__ float g_sy[NB * KP];         // src.y + eps
__device__ float g_sp[NB * KP];         // u * |src|^2
__device__ float g_tx[NB * KP];         // trg.x
__device__ float g_ty[NB * KP];         // trg.y
__device__ float g_part[1024];          // per-block weighted loss partials
__device__ float g_cnt [1024];          // per-block visibility counts
__device__ int   g_ctr = 0;             // last-block counter (self-resetting)

// MUFU intrinsics -------------------------------------------------------------
__device__ __forceinline__ float lg2a(float x) { float y; asm("lg2.approx.f32 %0, %1;" : "=f"(y) : "f"(x)); return y; }
__device__ __forceinline__ float ex2_neg(float x) {
    float y; asm("{ .reg .f32 t; neg.f32 t, %1; ex2.approx.f32 %0, t; }" : "=f"(y) : "f"(x)); return y;
}
__device__ __forceinline__ float sqrt_abs(float x) {
    float y; asm("{ .reg .f32 t; abs.f32 t, %1; sqrt.approx.f32 %0, t; }" : "=f"(y) : "f"(x)); return y;
}

// Packed f32x2 helpers --------------------------------------------------------
typedef unsigned long long u64;
__device__ __forceinline__ u64 pack2(float v) {
    u64 r; asm("mov.b64 %0, {%1, %1};" : "=l"(r) : "f"(v)); return r;
}
__device__ __forceinline__ u64 pack2f(float lo, float hi) {
    u64 r; asm("mov.b64 %0, {%1, %2};" : "=l"(r) : "f"(lo), "f"(hi)); return r;
}
__device__ __forceinline__ u64 add2(u64 a, u64 b) {
    u64 r; asm("add.rn.f32x2 %0, %1, %2;" : "=l"(r) : "l"(a), "l"(b)); return r;
}
__device__ __forceinline__ u64 fma2(u64 a, u64 b, u64 c) {
    u64 r; asm("fma.rn.f32x2 %0, %1, %2, %3;" : "=l"(r) : "l"(a), "l"(b), "l"(c)); return r;
}
__device__ __forceinline__ void unpack2(u64 p, float& lo, float& hi) {
    asm("mov.b64 {%0, %1}, %2;" : "=f"(lo), "=f"(hi) : "l"(p));
}

// Kernel 1: corner-parallel bilinear sampling (SoA outputs, src+trg) ----------
__global__ __launch_bounds__(256) void sample_kernel(
        const float* __restrict__ sflow, const float* __restrict__ tflow,
        const float* __restrict__ skp,  const float* __restrict__ tkp) {
    int g      = blockIdx.x * blockDim.x + threadIdx.x;    // [0, 262144)
    int samp   = g >> 2;                                   // [0, 2*N*K)
    int corner = g & 3;                                    // dx = c&1, dy = c>>1
    int k      = samp & (NB * KP - 1);                     // n*K + kp
    int n      = k >> 10;
    bool is_src = samp < NB * KP;

    const float* kp   = is_src ? skp   : tkp;
    const float* flow = is_src ? sflow : tflow;
    float2 p = ((const float2*)kp)[k];

    float x0f = floorf(p.x), y0f = floorf(p.y);
    float wx  = p.x - x0f,   wy  = p.y - y0f;
    int dx = corner & 1, dy = corner >> 1;
    int xi = (int)x0f + dx, yi = (int)y0f + dy;
    float w = (dx ? wx : 1.f - wx) * (dy ? wy : 1.f - wy);

    float ax = 0.f, ay = 0.f;
    if (xi >= 0 && xi < RESO && yi >= 0 && yi < RESO) {
        const float2 v = *(const float2*)(flow + ((((size_t)n * RESO + yi) * RESO + xi) << 1));
        ax = v.x * w;
        ay = v.y * w;
    }
    ax += __shfl_xor_sync(0xffffffffu, ax, 1);
    ay += __shfl_xor_sync(0xffffffffu, ay, 1);
    ax += __shfl_xor_sync(0xffffffffu, ax, 2);
    ay += __shfl_xor_sync(0xffffffffu, ay, 2);

    if (corner == 0) {
        if (is_src) {
            float sx = ax + EPSF, sy = ay + EPSF;          // fold +eps into src side
            g_sx[k] = sx;
            g_sy[k] = sy;
            g_sp[k] = UF * fmaf(sx, sx, sy * sy);          // u*|s|^2
        } else {
            g_tx[k] = ax;
            g_ty[k] = ay;
        }
    }
}

// Kernel 2: pairwise + CE diag + fused reduction ------------------------------
// Hybrid exp: q0,q1 use MUFU ex2; q2,q3 use fixed-pipe poly 2^-t =
// 2^-round(t) * poly(t - round(t)). Balances MUFU vs FMA pipe load.
// 1 warp = 4 j's, block = 8 warps = 32 j's, grid = 1024.
__global__ __launch_bounds__(256) void pair_kernel(const int* __restrict__ vis,
                                                   const float* __restrict__ wt,
                                                   float* __restrict__ out) {
    __shared__ float shx[KP], shy[KP], shp[KP];            // src SoA for batch n (12 KB)
    __shared__ float sh_l[8], sh_v[8];
    __shared__ bool  s_last;
    const int warp = threadIdx.x >> 5, lane = threadIdx.x & 31;
    const int n     = blockIdx.x >> 5;                     // 32 blocks per batch
    const int jbase = ((blockIdx.x & 31) << 5) + (warp << 2);

    {   // vectorized smem fill: 256 float4 per array
        const float4* gx = (const float4*)(g_sx + n * KP);
        const float4* gy = (const float4*)(g_sy + n * KP);
        const float4* gp = (const float4*)(g_sp + n * KP);
        ((float4*)shx)[threadIdx.x] = gx[threadIdx.x];
        ((float4*)shy)[threadIdx.x] = gy[threadIdx.x];
        ((float4*)shp)[threadIdx.x] = gp[threadIdx.x];
    }
    __syncthreads();

    // per-j constants
    u64 qx2[4], qy2[4], rr2[4];
    float qxs[4], qys[4], rrs[4];
#pragma unroll
    for (int q = 0; q < 4; q++) {
        float txq = g_tx[n * KP + jbase + q];
        float tyq = g_ty[n * KP + jbase + q];
        qxs[q] = -2.f * UF * txq;
        qys[q] = -2.f * UF * tyq;
        rrs[q] = UF * fmaf(txq, txq, tyq * tyq);
        qx2[q] = pack2(qxs[q]);
        qy2[q] = pack2(qys[q]);
        rr2[q] = pack2(rrs[q]);
    }

    // packed constants for the poly-exp route (q2, q3 only)
    const u64 MAGIC2  = pack2(12582912.0f);                // 1.5 * 2^23
    const u64 NMAGIC2 = pack2(-12582912.0f);
    const u64 NEG1_2  = pack2(-1.0f);
    const u64 ONE_2   = pack2(1.0f);
    const u64 Cc1 = pack2(-0.69314718056f);                // Taylor of 2^-f, f in [-1/2,1/2]
    const u64 Cc2 = pack2( 0.24022650700f);
    const u64 Cc3 = pack2(-0.05550410866f);
    const u64 Cc4 = pack2( 0.00961812911f);

    u64 acc2[4] = {0ull, 0ull, 0ull, 0ull};                // packed f32x2 accumulators
    const u64* px = (const u64*)shx;                       // consecutive-i packed pairs
    const u64* py = (const u64*)shy;
    const u64* pp = (const u64*)shp;
#pragma unroll 4
    for (int it = 0; it < KP / 2; it += 32) {
        int pi = it + lane;
        u64 x2 = px[pi], y2 = py[pi], p2 = pp[pi];

        // ---- q0, q1: MUFU ex2 route ----
#pragma unroll
        for (int q = 0; q < 2; q++) {
            u64 d2 = fma2(x2, qx2[q], fma2(y2, qy2[q], add2(p2, rr2[q])));
            float dlo, dhi; unpack2(d2, dlo, dhi);
            float elo = ex2_neg(sqrt_abs(dlo));            // exp(-dist)
            float ehi = ex2_neg(sqrt_abs(dhi));
            acc2[q] = add2(acc2[q], pack2f(elo, ehi));
        }
        // ---- q2, q3: fixed-pipe poly route ----
#pragma unroll
        for (int q = 2; q < 4; q++) {
            u64 d2 = fma2(x2, qx2[q], fma2(y2, qy2[q], add2(p2, rr2[q])));
            float dlo, dhi; unpack2(d2, dlo, dhi);
            u64 tp = pack2f(sqrt_abs(dlo), sqrt_abs(dhi)); // t = C1*d (<~30, magic-safe)
            u64 rp = add2(tp, MAGIC2);
            u64 fp = fma2(add2(rp, NMAGIC2), NEG1_2, tp);  // f = t - round(t)
            float rlo, rhi; unpack2(rp, rlo, rhi);
            int slo = 0x3F800000 - __float_as_int(rlo) * 8388608;   // 2^-n bits
            int shi = 0x3F800000 - __float_as_int(rhi) * 8388608;
            u64 sp = pack2f(__int_as_float(slo), __int_as_float(shi));
            u64 pl = fma2(Cc4, fp, Cc3);
            pl = fma2(pl, fp, Cc2);
            pl = fma2(pl, fp, Cc1);
            pl = fma2(pl, fp, ONE_2);                      // ~= 2^-f
            acc2[q] = fma2(pl, sp, acc2[q]);
        }
    }
    // collapse packed accumulators and warp-reduce
    float a[4];
#pragma unroll
    for (int q = 0; q < 4; q++) {
        float lo, hi; unpack2(acc2[q], lo, hi);
        a[q] = lo + hi;
#pragma unroll
        for (int o = 16; o; o >>= 1)
            a[q] += __shfl_xor_sync(0xffffffffu, a[q], o);
    }

    if (lane == 0) {
        float lsum = 0.f, vsum = 0.f;
#pragma unroll
        for (int q = 0; q < 4; q++) {
            int j = jbase + q;
            // scaled diagonal: v_jj = C1 * dist_jj (same dot form)
            float dsq = fmaf(shx[j], qxs[q], fmaf(shy[j], qys[q], shp[j] + rrs[q]));
            float vjj = sqrt_abs(dsq);
            // loss = 2*(ln(acc) + dist_jj) = 2*ln2*(lg2(acc) + v_jj)
            float loss = (2.f * LN2F) * (lg2a(a[q]) + vjj);
            float vi = vis[n * KP + j] ? 1.f : 0.f;
            lsum = fmaf(loss * wt[n * KP + j], vi, lsum);
            vsum += vi;
        }
        sh_l[warp] = lsum; sh_v[warp] = vsum;
    }
    __syncthreads();

    if (threadIdx.x == 0) {
        float l = 0.f, v = 0.f;
#pragma unroll
        for (int w = 0; w < 8; w++) { l += sh_l[w]; v += sh_v[w]; }
        g_part[blockIdx.x] = l;
        g_cnt [blockIdx.x] = v;
        __threadfence();
        int prev = atomicAdd(&g_ctr, 1);
        s_last = (prev == 1023);
    }
    __syncthreads();

    // Last block performs the final deterministic fixed-tree reduce.
    if (s_last) {
        __shared__ float fl[8], fv[8];
        float l = 0.f, v = 0.f;
#pragma unroll
        for (int r = 0; r < 4; r++) {
            int i = threadIdx.x + (r << 8);
            l += g_part[i];
            v += g_cnt [i];
        }
#pragma unroll
        for (int o = 16; o; o >>= 1) {
            l += __shfl_xor_sync(0xffffffffu, l, o);
            v += __shfl_xor_sync(0xffffffffu, v, o);
        }
        if (lane == 0) { fl[warp] = l; fv[warp] = v; }
        __syncthreads();
        if (threadIdx.x == 0) {
            l = 0.f; v = 0.f;
#pragma unroll
            for (int w = 0; w < 8; w++) { l += fl[w]; v += fv[w]; }
            out[0] = l / v;
            g_ctr = 0;                                     // reset for next graph replay
        }
    }
}

extern "C" void kernel_launch(void* const* d_in, const int* in_sizes, int n_in,
                              void* d_out, int out_size) {
    const float* sflow = (const float*)d_in[0];
    const float* tflow = (const float*)d_in[1];
    const float* skp   = (const float*)d_in[2];
    const float* tkp   = (const float*)d_in[3];
    const int*   vis   = (const int*)d_in[4];   // bool serialized as int32
    const float* wt    = (const float*)d_in[5];
    float*       out   = (float*)d_out;

    sample_kernel<<<(2 * NB * KP * 4) / 256, 256>>>(sflow, tflow, skp, tkp);
    pair_kernel<<<1024, 256>>>(vis, wt, out);
}